// round 4
// baseline (speedup 1.0000x reference)
#include <cuda_runtime.h>

#define NN 4096
#define MM 4096
#define DD 8

typedef unsigned long long u64;

// out[i][j] = exp2( an[i] + bn[j] + sum_d a[i][d]*b[j][d] )
//   a = x/scale * sqrt(log2 e),  an = -0.5||a||^2 + log2(var),  bn = -0.5||b||^2

__device__ __forceinline__ u64 fma2(u64 a, u64 b, u64 c) {
    u64 d; asm("fma.rn.f32x2 %0, %1, %2, %3;" : "=l"(d) : "l"(a), "l"(b), "l"(c)); return d;
}
__device__ __forceinline__ u64 add2(u64 a, u64 b) {
    u64 d; asm("add.rn.f32x2 %0, %1, %2;" : "=l"(d) : "l"(a), "l"(b)); return d;
}
__device__ __forceinline__ u64 pack2(float x, float y) {
    u64 r; asm("mov.b64 %0, {%1,%2};" : "=l"(r) : "f"(x), "f"(y)); return r;
}
__device__ __forceinline__ float lo2(u64 v) { return __uint_as_float((unsigned)v); }
__device__ __forceinline__ float hi2(u64 v) { return __uint_as_float((unsigned)(v >> 32)); }
__device__ __forceinline__ float ex2(float x) {
    float r; asm("ex2.approx.f32 %0, %1;" : "=f"(r) : "f"(x)); return r;
}

// One fused kernel. CTA tile: 64 (i) x 128 (j), 256 threads, 32 outputs/thread.
// launch_bounds(256,5): cap regs at ~51 so 5 CTAs (40 warps) fit per SM.
__global__ __launch_bounds__(256, 5) void rbf_main(
    const float* __restrict__ x,
    const float* __restrict__ xx,
    const float* __restrict__ log_scale,
    const float* __restrict__ log_variance,
    float* __restrict__ out)
{
    __shared__ float  s_inv[DD];       // 1/scale * sqrt(log2 e)
    __shared__ u64    sA2[64][DD];     // pre-splatted {a,a}       (4KB)
    __shared__ float  sB [DD][128];    // b, d-major               (4KB)
    __shared__ u64    sAn2[64];        // pre-splatted {an,an}
    __shared__ float  sBn[128];

    const int bi = blockIdx.y * 64;
    const int bj = blockIdx.x * 128;
    const int tid = threadIdx.x;

    if (tid < DD) {
        s_inv[tid] = ex2(-log_scale[tid] * 1.4426950408889634f) * 1.2011224087864498f;
    }
    __syncthreads();

    // ---- fused prep ----
    if (tid < 64) {
        const float4 p0 = ((const float4*)(x + (size_t)(bi + tid) * DD))[0];
        const float4 p1 = ((const float4*)(x + (size_t)(bi + tid) * DD))[1];
        float a[DD];
        a[0] = p0.x * s_inv[0]; a[1] = p0.y * s_inv[1];
        a[2] = p0.z * s_inv[2]; a[3] = p0.w * s_inv[3];
        a[4] = p1.x * s_inv[4]; a[5] = p1.y * s_inv[5];
        a[6] = p1.z * s_inv[6]; a[7] = p1.w * s_inv[7];
        float s = 0.f;
        #pragma unroll
        for (int d = 0; d < DD; d++) { sA2[tid][d] = pack2(a[d], a[d]); s = fmaf(a[d], a[d], s); }
        const float an = fmaf(-0.5f, s, log_variance[0] * 1.4426950408889634f);
        sAn2[tid] = pack2(an, an);
    } else if (tid < 192) {
        const int j = tid - 64;
        const float4 p0 = ((const float4*)(xx + (size_t)(bj + j) * DD))[0];
        const float4 p1 = ((const float4*)(xx + (size_t)(bj + j) * DD))[1];
        float b[DD];
        b[0] = p0.x * s_inv[0]; b[1] = p0.y * s_inv[1];
        b[2] = p0.z * s_inv[2]; b[3] = p0.w * s_inv[3];
        b[4] = p1.x * s_inv[4]; b[5] = p1.y * s_inv[5];
        b[6] = p1.z * s_inv[6]; b[7] = p1.w * s_inv[7];
        float s = 0.f;
        #pragma unroll
        for (int d = 0; d < DD; d++) { sB[d][j] = b[d]; s = fmaf(b[d], b[d], s); }
        sBn[j] = -0.5f * s;
    }
    __syncthreads();

    // ---- main compute ----
    const int ti = tid >> 4;   // 0..15, i = ti + 16u
    const int tj = tid & 15;   // 0..15, j quads at 4*tj and 64+4*tj

    u64 e[4][4];
    {
        const ulonglong2 bnA = *(const ulonglong2*)&sBn[4 * tj];
        const ulonglong2 bnB = *(const ulonglong2*)&sBn[64 + 4 * tj];
        #pragma unroll
        for (int u = 0; u < 4; u++) {
            const u64 anu = sAn2[ti + 16 * u];
            e[u][0] = add2(anu, bnA.x);
            e[u][1] = add2(anu, bnA.y);
            e[u][2] = add2(anu, bnB.x);
            e[u][3] = add2(anu, bnB.y);
        }
    }

    #pragma unroll
    for (int d = 0; d < DD; d++) {
        const ulonglong2 bA = *(const ulonglong2*)&sB[d][4 * tj];
        const ulonglong2 bB = *(const ulonglong2*)&sB[d][64 + 4 * tj];
        #pragma unroll
        for (int u = 0; u < 4; u++) {
            const u64 aa = sA2[ti + 16 * u][d];
            e[u][0] = fma2(aa, bA.x, e[u][0]);
            e[u][1] = fma2(aa, bA.y, e[u][1]);
            e[u][2] = fma2(aa, bB.x, e[u][2]);
            e[u][3] = fma2(aa, bB.y, e[u][3]);
        }
    }

    // epilogue: exp2 + vector stores
    float* p0 = out + (size_t)(bi + ti) * MM + bj + 4 * tj;
    #pragma unroll
    for (int u = 0; u < 4; u++) {
        float4 rA, rB;
        rA.x = ex2(lo2(e[u][0])); rA.y = ex2(hi2(e[u][0]));
        rA.z = ex2(lo2(e[u][1])); rA.w = ex2(hi2(e[u][1]));
        rB.x = ex2(lo2(e[u][2])); rB.y = ex2(hi2(e[u][2]));
        rB.z = ex2(lo2(e[u][3])); rB.w = ex2(hi2(e[u][3]));
        *(float4*)(p0)      = rA;
        *(float4*)(p0 + 64) = rB;
        p0 += (size_t)16 * MM;
    }
}

extern "C" void kernel_launch(void* const* d_in, const int* in_sizes, int n_in,
                              void* d_out, int out_size) {
    const float* x      = (const float*)d_in[0];
    const float* xx     = (const float*)d_in[1];
    const float* lscale = (const float*)d_in[2];
    const float* lvar   = (const float*)d_in[3];
    float* out          = (float*)d_out;

    dim3 grid(MM / 128, NN / 64);
    rbf_main<<<grid, 256>>>(x, xx, lscale, lvar, out);
}

// round 5
// speedup vs baseline: 1.8501x; 1.8501x over previous
#include <cuda_runtime.h>

#define NN 4096
#define MM 4096
#define DD 8

typedef unsigned long long u64;

// out[i][j] = exp2( an[i] + bn[j] + sum_d a[i][d]*b[j][d] )
//   a = x/scale * sqrt(log2 e),  an = -0.5||a||^2 + log2(var),  bn = -0.5||b||^2

__device__ __forceinline__ u64 fma2(u64 a, u64 b, u64 c) {
    u64 d; asm("fma.rn.f32x2 %0, %1, %2, %3;" : "=l"(d) : "l"(a), "l"(b), "l"(c)); return d;
}
__device__ __forceinline__ u64 add2(u64 a, u64 b) {
    u64 d; asm("add.rn.f32x2 %0, %1, %2;" : "=l"(d) : "l"(a), "l"(b)); return d;
}
__device__ __forceinline__ u64 pack2(float x, float y) {
    u64 r; asm("mov.b64 %0, {%1,%2};" : "=l"(r) : "f"(x), "f"(y)); return r;
}
__device__ __forceinline__ float lo2(u64 v) { return __uint_as_float((unsigned)v); }
__device__ __forceinline__ float hi2(u64 v) { return __uint_as_float((unsigned)(v >> 32)); }
__device__ __forceinline__ float ex2(float x) {
    float r; asm("ex2.approx.f32 %0, %1;" : "=f"(r) : "f"(x)); return r;
}

// Fused kernel. CTA tile: 64 (i) x 128 (j), 256 threads, 32 outputs/thread.
// i = bi + 4*ti + u  (consecutive-i register tile: aa operands pair into LDS.128)
// j quads at bj + 4*tj and bj + 64 + 4*tj
__global__ __launch_bounds__(256, 4) void rbf_main(
    const float* __restrict__ x,
    const float* __restrict__ xx,
    const float* __restrict__ log_scale,
    const float* __restrict__ log_variance,
    float* __restrict__ out)
{
    __shared__ float  s_inv[DD];        // 1/scale * sqrt(log2 e)
    __shared__ u64    sA2[DD][64];      // d-major, pre-splatted {a,a}   (4KB)
    __shared__ float  sB [DD][128];     // d-major b                     (4KB)
    __shared__ u64    sAn2[64];         // pre-splatted {an,an}
    __shared__ float  sBn[128];

    const int bi = blockIdx.y * 64;
    const int bj = blockIdx.x * 128;
    const int tid = threadIdx.x;

    if (tid < DD) {
        s_inv[tid] = ex2(-log_scale[tid] * 1.4426950408889634f) * 1.2011224087864498f;
    }
    __syncthreads();

    // ---- fused prep ----
    if (tid < 64) {
        const float4 p0 = ((const float4*)(x + (size_t)(bi + tid) * DD))[0];
        const float4 p1 = ((const float4*)(x + (size_t)(bi + tid) * DD))[1];
        float a[DD];
        a[0] = p0.x * s_inv[0]; a[1] = p0.y * s_inv[1];
        a[2] = p0.z * s_inv[2]; a[3] = p0.w * s_inv[3];
        a[4] = p1.x * s_inv[4]; a[5] = p1.y * s_inv[5];
        a[6] = p1.z * s_inv[6]; a[7] = p1.w * s_inv[7];
        float s = 0.f;
        #pragma unroll
        for (int d = 0; d < DD; d++) { sA2[d][tid] = pack2(a[d], a[d]); s = fmaf(a[d], a[d], s); }
        const float an = fmaf(-0.5f, s, log_variance[0] * 1.4426950408889634f);
        sAn2[tid] = pack2(an, an);
    } else if (tid < 192) {
        const int j = tid - 64;
        const float4 p0 = ((const float4*)(xx + (size_t)(bj + j) * DD))[0];
        const float4 p1 = ((const float4*)(xx + (size_t)(bj + j) * DD))[1];
        float b[DD];
        b[0] = p0.x * s_inv[0]; b[1] = p0.y * s_inv[1];
        b[2] = p0.z * s_inv[2]; b[3] = p0.w * s_inv[3];
        b[4] = p1.x * s_inv[4]; b[5] = p1.y * s_inv[5];
        b[6] = p1.z * s_inv[6]; b[7] = p1.w * s_inv[7];
        float s = 0.f;
        #pragma unroll
        for (int d = 0; d < DD; d++) { sB[d][j] = b[d]; s = fmaf(b[d], b[d], s); }
        sBn[j] = -0.5f * s;
    }
    __syncthreads();

    // ---- main compute ----
    const int ti = tid >> 4;   // 0..15, i = 4*ti + u
    const int tj = tid & 15;   // 0..15

    u64 e[4][4];
    {
        const ulonglong2 bnA = *(const ulonglong2*)&sBn[4 * tj];
        const ulonglong2 bnB = *(const ulonglong2*)&sBn[64 + 4 * tj];
        const ulonglong2 an01 = *(const ulonglong2*)&sAn2[4 * ti];
        const ulonglong2 an23 = *(const ulonglong2*)&sAn2[4 * ti + 2];
        const u64 anv[4] = {an01.x, an01.y, an23.x, an23.y};
        #pragma unroll
        for (int u = 0; u < 4; u++) {
            e[u][0] = add2(anv[u], bnA.x);
            e[u][1] = add2(anv[u], bnA.y);
            e[u][2] = add2(anv[u], bnB.x);
            e[u][3] = add2(anv[u], bnB.y);
        }
    }

    #pragma unroll
    for (int d = 0; d < DD; d++) {
        const ulonglong2 bA = *(const ulonglong2*)&sB[d][4 * tj];
        const ulonglong2 bB = *(const ulonglong2*)&sB[d][64 + 4 * tj];
        const ulonglong2 a01 = *(const ulonglong2*)&sA2[d][4 * ti];
        const ulonglong2 a23 = *(const ulonglong2*)&sA2[d][4 * ti + 2];
        const u64 av[4] = {a01.x, a01.y, a23.x, a23.y};
        #pragma unroll
        for (int u = 0; u < 4; u++) {
            e[u][0] = fma2(av[u], bA.x, e[u][0]);
            e[u][1] = fma2(av[u], bA.y, e[u][1]);
            e[u][2] = fma2(av[u], bB.x, e[u][2]);
            e[u][3] = fma2(av[u], bB.y, e[u][3]);
        }
    }

    // epilogue: exp2 + vector stores; rows bi + 4*ti + u are consecutive
    float* p0 = out + (size_t)(bi + 4 * ti) * MM + bj + 4 * tj;
    #pragma unroll
    for (int u = 0; u < 4; u++) {
        float4 rA, rB;
        rA.x = ex2(lo2(e[u][0])); rA.y = ex2(hi2(e[u][0]));
        rA.z = ex2(lo2(e[u][1])); rA.w = ex2(hi2(e[u][1]));
        rB.x = ex2(lo2(e[u][2])); rB.y = ex2(hi2(e[u][2]));
        rB.z = ex2(lo2(e[u][3])); rB.w = ex2(hi2(e[u][3]));
        *(float4*)(p0)      = rA;
        *(float4*)(p0 + 64) = rB;
        p0 += MM;
    }
}

extern "C" void kernel_launch(void* const* d_in, const int* in_sizes, int n_in,
                              void* d_out, int out_size) {
    const float* x      = (const float*)d_in[0];
    const float* xx     = (const float*)d_in[1];
    const float* lscale = (const float*)d_in[2];
    const float* lvar   = (const float*)d_in[3];
    float* out          = (float*)d_out;

    dim3 grid(MM / 128, NN / 64);
    rbf_main<<<grid, 256>>>(x, xx, lscale, lvar, out);
}